// round 1
// baseline (speedup 1.0000x reference)
#include <cuda_runtime.h>
#include <math.h>

// Problem constants (match reference)
#define NMAX 100000
#define EMAX 1600000
#define H 128
#define C 40

// Scratch (static __device__ arrays — allocation-free per harness rules)
__device__ float g_dinv[NMAX];          // degree -> rsqrt(degree), in place
__device__ float g_lin[(size_t)NMAX * H];   // GEMM output
__device__ float g_agg[(size_t)NMAX * H];   // aggregation accumulator
__device__ float g_h0 [(size_t)NMAX * H];   // layer-0 activation (residual)

// ---------------------------------------------------------------------------
// degree / dinv
// ---------------------------------------------------------------------------
__global__ void k_fill(float* p, float val, int n) {
    int i = blockIdx.x * blockDim.x + threadIdx.x;
    if (i < n) p[i] = val;
}

__global__ void k_deg(const int* __restrict__ dst, float* deg, int e) {
    int i = blockIdx.x * blockDim.x + threadIdx.x;
    if (i < e) atomicAdd(&deg[dst[i]], 1.0f);
}

__global__ void k_rsqrt(float* p, int n) {
    int i = blockIdx.x * blockDim.x + threadIdx.x;
    if (i < n) p[i] = rsqrtf(p[i]);
}

// ---------------------------------------------------------------------------
// GEMM: C[M,128] = A[M,128] @ B[128,128]   (fp32, BM=64 BN=128 BK=16)
// 256 threads: thread tile 8 rows x 4 cols
// ---------------------------------------------------------------------------
__global__ void k_gemm128(const float* __restrict__ A,
                          const float* __restrict__ B,
                          float* __restrict__ Cm, int M) {
    __shared__ float As[64][17];     // +1 pad: conflict-free column reads
    __shared__ float Bs[16][128];

    const int tx = threadIdx.x & 31;   // 0..31 -> col group (tx*4)
    const int ty = threadIdx.x >> 5;   // 0..7  -> row group (ty*8)
    const int rowBase = blockIdx.x * 64;

    float acc[8][4];
#pragma unroll
    for (int i = 0; i < 8; i++)
#pragma unroll
        for (int j = 0; j < 4; j++) acc[i][j] = 0.0f;

    for (int k0 = 0; k0 < 128; k0 += 16) {
        // load A tile: 64x16 floats, one float4 per thread
        {
            int t  = threadIdx.x;
            int r  = t >> 2;             // 0..63
            int c4 = (t & 3) << 2;       // 0,4,8,12
            int gr = rowBase + r;
            float4 v = make_float4(0.f, 0.f, 0.f, 0.f);
            if (gr < M) v = *(const float4*)(A + (size_t)gr * 128 + k0 + c4);
            As[r][c4 + 0] = v.x; As[r][c4 + 1] = v.y;
            As[r][c4 + 2] = v.z; As[r][c4 + 3] = v.w;
        }
        // load B tile: 16x128 floats, two float4 per thread
        {
#pragma unroll
            for (int i = 0; i < 2; i++) {
                int idx = threadIdx.x + i * 256;   // 0..511
                int r   = idx >> 5;                // 0..15
                int c4  = (idx & 31) << 2;
                float4 v = *(const float4*)(B + (size_t)(k0 + r) * 128 + c4);
                *(float4*)&Bs[r][c4] = v;
            }
        }
        __syncthreads();

#pragma unroll
        for (int kk = 0; kk < 16; kk++) {
            float4 bv = *(const float4*)&Bs[kk][tx << 2];
#pragma unroll
            for (int i = 0; i < 8; i++) {
                float a = As[ty * 8 + i][kk];
                acc[i][0] = fmaf(a, bv.x, acc[i][0]);
                acc[i][1] = fmaf(a, bv.y, acc[i][1]);
                acc[i][2] = fmaf(a, bv.z, acc[i][2]);
                acc[i][3] = fmaf(a, bv.w, acc[i][3]);
            }
        }
        __syncthreads();
    }

#pragma unroll
    for (int i = 0; i < 8; i++) {
        int gr = rowBase + ty * 8 + i;
        if (gr < M) {
            float4 v = make_float4(acc[i][0], acc[i][1], acc[i][2], acc[i][3]);
            *(float4*)(Cm + (size_t)gr * 128 + (tx << 2)) = v;
        }
    }
}

// ---------------------------------------------------------------------------
// self-loop init: agg[v,:] = dinv[v]^2 * lin[v,:]   (grid over N*32 float4s)
// ---------------------------------------------------------------------------
__global__ void k_selfloop(const float* __restrict__ lin,
                           const float* __restrict__ dinv,
                           float* __restrict__ agg, int nq) {
    int i = blockIdx.x * blockDim.x + threadIdx.x;
    if (i >= nq) return;
    int v = i >> 5;                    // 32 float4s per row
    float d = dinv[v];
    float s = d * d;
    float4 x = ((const float4*)lin)[i];
    x.x *= s; x.y *= s; x.z *= s; x.w *= s;
    ((float4*)agg)[i] = x;
}

// ---------------------------------------------------------------------------
// edge scatter: warp per edge; lane handles float4 of 128-wide row
// agg[dst,:] += dinv[src]*dinv[dst] * lin[src,:]
// ---------------------------------------------------------------------------
__global__ void k_edge(const int* __restrict__ src,
                       const int* __restrict__ dst,
                       const float* __restrict__ dinv,
                       const float* __restrict__ lin,
                       float* __restrict__ agg, int e) {
    int w = (blockIdx.x * blockDim.x + threadIdx.x) >> 5;
    int lane = threadIdx.x & 31;
    if (w >= e) return;
    int s = src[w];
    int d = dst[w];
    float norm = dinv[s] * dinv[d];
    float4 v = *(const float4*)(lin + (size_t)s * 128 + (lane << 2));
    float* o = agg + (size_t)d * 128 + (lane << 2);
    atomicAdd(o + 0, norm * v.x);
    atomicAdd(o + 1, norm * v.y);
    atomicAdd(o + 2, norm * v.z);
    atomicAdd(o + 3, norm * v.w);
}

// ---------------------------------------------------------------------------
// epilogue: out = relu(agg + b) [+ res]
// ---------------------------------------------------------------------------
__global__ void k_bias_relu(const float* __restrict__ agg,
                            const float* __restrict__ b,
                            const float* __restrict__ res,   // may be nullptr
                            float* __restrict__ out, int nq) {
    int i = blockIdx.x * blockDim.x + threadIdx.x;
    if (i >= nq) return;
    int f4 = i & 31;
    float4 bb = ((const float4*)b)[f4];
    float4 v = ((const float4*)agg)[i];
    v.x = fmaxf(v.x + bb.x, 0.f);
    v.y = fmaxf(v.y + bb.y, 0.f);
    v.z = fmaxf(v.z + bb.z, 0.f);
    v.w = fmaxf(v.w + bb.w, 0.f);
    if (res) {
        float4 r = ((const float4*)res)[i];
        v.x += r.x; v.y += r.y; v.z += r.z; v.w += r.w;
    }
    ((float4*)out)[i] = v;
}

// ---------------------------------------------------------------------------
// classifier: out[r,:] = log_softmax(h[r,:] @ wl + bl), warp per row
// wl stored transposed in smem as [c][128] for conflict-free float4 reads
// ---------------------------------------------------------------------------
__global__ void k_cls(const float* __restrict__ h,
                      const float* __restrict__ wl,
                      const float* __restrict__ bl,
                      float* __restrict__ out, int nrows) {
    __shared__ float swl[C * 128];   // transposed [c][k], 20KB
    __shared__ float sbl[C];
    for (int i = threadIdx.x; i < C * 128; i += blockDim.x) {
        int k = i / C, c = i % C;
        swl[c * 128 + k] = wl[i];
    }
    if (threadIdx.x < C) sbl[threadIdx.x] = bl[threadIdx.x];
    __syncthreads();

    const int lane = threadIdx.x & 31;
    const int warp = (blockIdx.x * blockDim.x + threadIdx.x) >> 5;
    const int nwarps = (gridDim.x * blockDim.x) >> 5;

    for (int r = warp; r < nrows; r += nwarps) {
        float4 hr = *(const float4*)(h + (size_t)r * 128 + (lane << 2));
        float l0 = 0.f, l1 = 0.f;   // lane holds logits c=lane, c=lane+32
#pragma unroll
        for (int c = 0; c < C; c++) {
            float4 w = *(const float4*)&swl[c * 128 + (lane << 2)];
            float p = hr.x * w.x + hr.y * w.y + hr.z * w.z + hr.w * w.w;
            p += __shfl_xor_sync(0xffffffffu, p, 16);
            p += __shfl_xor_sync(0xffffffffu, p, 8);
            p += __shfl_xor_sync(0xffffffffu, p, 4);
            p += __shfl_xor_sync(0xffffffffu, p, 2);
            p += __shfl_xor_sync(0xffffffffu, p, 1);
            p += sbl[c];
            if (c == lane)      l0 = p;
            if (c == lane + 32) l1 = p;
        }
        float m = l0;
        if (lane < C - 32) m = fmaxf(m, l1);
#pragma unroll
        for (int o = 16; o; o >>= 1) m = fmaxf(m, __shfl_xor_sync(0xffffffffu, m, o));
        float se = __expf(l0 - m) + ((lane < C - 32) ? __expf(l1 - m) : 0.f);
#pragma unroll
        for (int o = 16; o; o >>= 1) se += __shfl_xor_sync(0xffffffffu, se, o);
        float lse = __logf(se) + m;
        out[(size_t)r * C + lane] = l0 - lse;
        if (lane < C - 32) out[(size_t)r * C + 32 + lane] = l1 - lse;
    }
}

// ---------------------------------------------------------------------------
// launch
// ---------------------------------------------------------------------------
extern "C" void kernel_launch(void* const* d_in, const int* in_sizes, int n_in,
                              void* d_out, int out_size) {
    const float* x   = (const float*)d_in[0];
    const int*   ei  = (const int*)d_in[1];
    const float* w0  = (const float*)d_in[2];
    const float* b0  = (const float*)d_in[3];
    const float* w1  = (const float*)d_in[4];
    const float* b1  = (const float*)d_in[5];
    const float* wl  = (const float*)d_in[6];
    const float* bl  = (const float*)d_in[7];
    float* out = (float*)d_out;

    const int n = in_sizes[0] / H;       // 100000
    const int e = in_sizes[1] / 2;       // 1600000
    const int* src = ei;
    const int* dst = ei + e;

    float *dinv, *lin, *agg, *h0;
    cudaGetSymbolAddress((void**)&dinv, g_dinv);
    cudaGetSymbolAddress((void**)&lin,  g_lin);
    cudaGetSymbolAddress((void**)&agg,  g_agg);
    cudaGetSymbolAddress((void**)&h0,   g_h0);

    const int nq = n * (H / 4);          // float4 count of N x H
    const int TB = 256;

    // degree -> dinv
    k_fill <<<(n + TB - 1) / TB, TB>>>(dinv, 1.0f, n);
    k_deg  <<<(e + TB - 1) / TB, TB>>>(dst, dinv, e);
    k_rsqrt<<<(n + TB - 1) / TB, TB>>>(dinv, n);

    const int gemmBlocks = (n + 63) / 64;
    const int edgeBlocks = (e * 32 + TB - 1) / TB;   // warp per edge
    const int eltBlocks  = (nq + TB - 1) / TB;

    // layer 0
    k_gemm128  <<<gemmBlocks, TB>>>(x, w0, lin, n);
    k_selfloop <<<eltBlocks, TB>>>(lin, dinv, agg, nq);
    k_edge     <<<edgeBlocks, TB>>>(src, dst, dinv, lin, agg, e);
    k_bias_relu<<<eltBlocks, TB>>>(agg, b0, nullptr, h0, nq);

    // layer 1 (+ residual)
    k_gemm128  <<<gemmBlocks, TB>>>(h0, w1, lin, n);
    k_selfloop <<<eltBlocks, TB>>>(lin, dinv, agg, nq);
    k_edge     <<<edgeBlocks, TB>>>(src, dst, dinv, lin, agg, e);
    k_bias_relu<<<eltBlocks, TB>>>(agg, b1, h0, lin, nq);   // lin <- h1

    // classifier + log_softmax
    k_cls<<<(n + 7) / 8, TB>>>(lin, wl, bl, out, n);
}

// round 2
// speedup vs baseline: 2.0057x; 2.0057x over previous
#include <cuda_runtime.h>
#include <math.h>

#define NMAX 100000
#define EMAX 1600000
#define H 128
#define C 40
#define SEG 512            // scan segment size

// ---------------- scratch (__device__ globals, allocation-free) ------------
__device__ float g_dinv[NMAX];
__device__ int   g_cnt[NMAX];
__device__ int   g_rowstart[NMAX + 1];
__device__ int   g_cursor[NMAX];
__device__ int   g_bsum[(NMAX + SEG - 1) / SEG];
__device__ int   g_csr_src[EMAX];
__device__ float g_csr_w[EMAX];
__device__ float g_lin[(size_t)NMAX * H];
__device__ float g_agg[(size_t)NMAX * H];
__device__ float g_h0 [(size_t)NMAX * H];

// ---------------------------------------------------------------------------
// CSR build
// ---------------------------------------------------------------------------
__global__ void k_zero_int(int* p, int n) {
    int i = blockIdx.x * blockDim.x + threadIdx.x;
    if (i < n) p[i] = 0;
}

__global__ void k_count(const int* __restrict__ dst, int* cnt, int e) {
    int i = blockIdx.x * blockDim.x + threadIdx.x;
    if (i < e) atomicAdd(&cnt[dst[i]], 1);
}

__global__ void k_dinv(const int* __restrict__ cnt, float* dinv, int n) {
    int i = blockIdx.x * blockDim.x + threadIdx.x;
    if (i < n) dinv[i] = rsqrtf((float)(cnt[i] + 1));   // +1 self loop
}

// pass 1: per-block inclusive scan of SEG counts -> exclusive local, block sum
__global__ void k_scan1(const int* __restrict__ cnt, int* rowstart,
                        int* bsum, int n) {
    __shared__ int sh[SEG];
    int i = blockIdx.x * SEG + threadIdx.x;
    int v = (i < n) ? cnt[i] : 0;
    sh[threadIdx.x] = v;
    __syncthreads();
#pragma unroll
    for (int o = 1; o < SEG; o <<= 1) {
        int t = (threadIdx.x >= o) ? sh[threadIdx.x - o] : 0;
        __syncthreads();
        sh[threadIdx.x] += t;
        __syncthreads();
    }
    if (i < n) rowstart[i] = sh[threadIdx.x] - v;     // exclusive
    if (threadIdx.x == SEG - 1) bsum[blockIdx.x] = sh[SEG - 1];
}

// pass 2: single block scans block sums (nb <= 256), writes total -> rowstart[n]
__global__ void k_scan2(int* bsum, int* rowstart, int nb, int n) {
    __shared__ int sh[256];
    int v = (threadIdx.x < nb) ? bsum[threadIdx.x] : 0;
    sh[threadIdx.x] = v;
    __syncthreads();
#pragma unroll
    for (int o = 1; o < 256; o <<= 1) {
        int t = (threadIdx.x >= o) ? sh[threadIdx.x - o] : 0;
        __syncthreads();
        sh[threadIdx.x] += t;
        __syncthreads();
    }
    if (threadIdx.x < nb) bsum[threadIdx.x] = sh[threadIdx.x] - v;  // exclusive
    if (threadIdx.x == 255) rowstart[n] = sh[255];                  // total = E
}

// pass 3: add block offsets; init cursor
__global__ void k_scan3(int* rowstart, const int* __restrict__ bsum,
                        int* cursor, int n) {
    int i = blockIdx.x * blockDim.x + threadIdx.x;
    if (i < n) {
        int r = rowstart[i] + bsum[i / SEG];
        rowstart[i] = r;
        cursor[i]   = r;
    }
}

// scatter edges into dst bins; precompute per-edge norm
__global__ void k_scatter(const int* __restrict__ src, const int* __restrict__ dst,
                          const float* __restrict__ dinv, int* cursor,
                          int* csr_src, float* csr_w, int e) {
    int i = blockIdx.x * blockDim.x + threadIdx.x;
    if (i >= e) return;
    int s = src[i], d = dst[i];
    int p = atomicAdd(&cursor[d], 1);
    csr_src[p] = s;
    csr_w[p]   = dinv[s] * dinv[d];
}

// ---------------------------------------------------------------------------
// GEMM: C[M,128] = A[M,128] @ B[128,128]  (fp32, BM=64 BN=128 BK=16)
// ---------------------------------------------------------------------------
__global__ void k_gemm128(const float* __restrict__ A,
                          const float* __restrict__ B,
                          float* __restrict__ Cm, int M) {
    __shared__ float As[64][17];
    __shared__ float Bs[16][128];

    const int tx = threadIdx.x & 31;
    const int ty = threadIdx.x >> 5;
    const int rowBase = blockIdx.x * 64;

    float acc[8][4];
#pragma unroll
    for (int i = 0; i < 8; i++)
#pragma unroll
        for (int j = 0; j < 4; j++) acc[i][j] = 0.0f;

    for (int k0 = 0; k0 < 128; k0 += 16) {
        {
            int t  = threadIdx.x;
            int r  = t >> 2;
            int c4 = (t & 3) << 2;
            int gr = rowBase + r;
            float4 v = make_float4(0.f, 0.f, 0.f, 0.f);
            if (gr < M) v = *(const float4*)(A + (size_t)gr * 128 + k0 + c4);
            As[r][c4 + 0] = v.x; As[r][c4 + 1] = v.y;
            As[r][c4 + 2] = v.z; As[r][c4 + 3] = v.w;
        }
#pragma unroll
        for (int i = 0; i < 2; i++) {
            int idx = threadIdx.x + i * 256;
            int r   = idx >> 5;
            int c4  = (idx & 31) << 2;
            float4 v = *(const float4*)(B + (size_t)(k0 + r) * 128 + c4);
            *(float4*)&Bs[r][c4] = v;
        }
        __syncthreads();

#pragma unroll
        for (int kk = 0; kk < 16; kk++) {
            float4 bv = *(const float4*)&Bs[kk][tx << 2];
#pragma unroll
            for (int i = 0; i < 8; i++) {
                float a = As[ty * 8 + i][kk];
                acc[i][0] = fmaf(a, bv.x, acc[i][0]);
                acc[i][1] = fmaf(a, bv.y, acc[i][1]);
                acc[i][2] = fmaf(a, bv.z, acc[i][2]);
                acc[i][3] = fmaf(a, bv.w, acc[i][3]);
            }
        }
        __syncthreads();
    }

#pragma unroll
    for (int i = 0; i < 8; i++) {
        int gr = rowBase + ty * 8 + i;
        if (gr < M) {
            float4 v = make_float4(acc[i][0], acc[i][1], acc[i][2], acc[i][3]);
            *(float4*)(Cm + (size_t)gr * 128 + (tx << 2)) = v;
        }
    }
}

// ---------------------------------------------------------------------------
// fused gather: warp per dst node
//   acc = dinv[v]^2 * lin[v] + sum_in_edges w * lin[src]
//   out = relu(acc + bias) [+ res]
// ---------------------------------------------------------------------------
__global__ void k_gather(const float* __restrict__ lin,
                         const float* __restrict__ dinv,
                         const int* __restrict__ rowstart,
                         const int* __restrict__ csr_src,
                         const float* __restrict__ csr_w,
                         const float* __restrict__ bias,
                         const float* __restrict__ res,    // may be nullptr
                         float* __restrict__ out, int n) {
    int v = (blockIdx.x * blockDim.x + threadIdx.x) >> 5;
    int lane = threadIdx.x & 31;
    if (v >= n) return;

    int beg = rowstart[v];
    int end = rowstart[v + 1];
    float dv = dinv[v];
    float sl = dv * dv;

    float4 acc = *(const float4*)(lin + (size_t)v * 128 + (lane << 2));
    acc.x *= sl; acc.y *= sl; acc.z *= sl; acc.w *= sl;

    int i = beg;
    // unroll-2 for MLP
    for (; i + 1 < end; i += 2) {
        int   s0 = csr_src[i];
        int   s1 = csr_src[i + 1];
        float w0 = csr_w[i];
        float w1 = csr_w[i + 1];
        float4 x0 = *(const float4*)(lin + (size_t)s0 * 128 + (lane << 2));
        float4 x1 = *(const float4*)(lin + (size_t)s1 * 128 + (lane << 2));
        acc.x = fmaf(w0, x0.x, acc.x); acc.y = fmaf(w0, x0.y, acc.y);
        acc.z = fmaf(w0, x0.z, acc.z); acc.w = fmaf(w0, x0.w, acc.w);
        acc.x = fmaf(w1, x1.x, acc.x); acc.y = fmaf(w1, x1.y, acc.y);
        acc.z = fmaf(w1, x1.z, acc.z); acc.w = fmaf(w1, x1.w, acc.w);
    }
    if (i < end) {
        int   s0 = csr_src[i];
        float w0 = csr_w[i];
        float4 x0 = *(const float4*)(lin + (size_t)s0 * 128 + (lane << 2));
        acc.x = fmaf(w0, x0.x, acc.x); acc.y = fmaf(w0, x0.y, acc.y);
        acc.z = fmaf(w0, x0.z, acc.z); acc.w = fmaf(w0, x0.w, acc.w);
    }

    float4 bb = ((const float4*)bias)[lane];
    acc.x = fmaxf(acc.x + bb.x, 0.f);
    acc.y = fmaxf(acc.y + bb.y, 0.f);
    acc.z = fmaxf(acc.z + bb.z, 0.f);
    acc.w = fmaxf(acc.w + bb.w, 0.f);
    if (res) {
        float4 r = *(const float4*)(res + (size_t)v * 128 + (lane << 2));
        acc.x += r.x; acc.y += r.y; acc.z += r.z; acc.w += r.w;
    }
    *(float4*)(out + (size_t)v * 128 + (lane << 2)) = acc;
}

// ---------------------------------------------------------------------------
// classifier: warp per row, log_softmax over 40 classes
// ---------------------------------------------------------------------------
__global__ void k_cls(const float* __restrict__ h,
                      const float* __restrict__ wl,
                      const float* __restrict__ bl,
                      float* __restrict__ out, int nrows) {
    __shared__ float swl[C * 128];
    __shared__ float sbl[C];
    for (int i = threadIdx.x; i < C * 128; i += blockDim.x) {
        int k = i / C, c = i % C;
        swl[c * 128 + k] = wl[i];
    }
    if (threadIdx.x < C) sbl[threadIdx.x] = bl[threadIdx.x];
    __syncthreads();

    const int lane = threadIdx.x & 31;
    const int warp = (blockIdx.x * blockDim.x + threadIdx.x) >> 5;
    const int nwarps = (gridDim.x * blockDim.x) >> 5;

    for (int r = warp; r < nrows; r += nwarps) {
        float4 hr = *(const float4*)(h + (size_t)r * 128 + (lane << 2));
        float l0 = 0.f, l1 = 0.f;
#pragma unroll
        for (int c = 0; c < C; c++) {
            float4 w = *(const float4*)&swl[c * 128 + (lane << 2)];
            float p = hr.x * w.x + hr.y * w.y + hr.z * w.z + hr.w * w.w;
            p += __shfl_xor_sync(0xffffffffu, p, 16);
            p += __shfl_xor_sync(0xffffffffu, p, 8);
            p += __shfl_xor_sync(0xffffffffu, p, 4);
            p += __shfl_xor_sync(0xffffffffu, p, 2);
            p += __shfl_xor_sync(0xffffffffu, p, 1);
            p += sbl[c];
            if (c == lane)      l0 = p;
            if (c == lane + 32) l1 = p;
        }
        float m = l0;
        if (lane < C - 32) m = fmaxf(m, l1);
#pragma unroll
        for (int o = 16; o; o >>= 1) m = fmaxf(m, __shfl_xor_sync(0xffffffffu, m, o));
        float se = __expf(l0 - m) + ((lane < C - 32) ? __expf(l1 - m) : 0.f);
#pragma unroll
        for (int o = 16; o; o >>= 1) se += __shfl_xor_sync(0xffffffffu, se, o);
        float lse = __logf(se) + m;
        out[(size_t)r * C + lane] = l0 - lse;
        if (lane < C - 32) out[(size_t)r * C + 32 + lane] = l1 - lse;
    }
}

// ---------------------------------------------------------------------------
// launch
// ---------------------------------------------------------------------------
extern "C" void kernel_launch(void* const* d_in, const int* in_sizes, int n_in,
                              void* d_out, int out_size) {
    const float* x   = (const float*)d_in[0];
    const int*   ei  = (const int*)d_in[1];
    const float* w0  = (const float*)d_in[2];
    const float* b0  = (const float*)d_in[3];
    const float* w1  = (const float*)d_in[4];
    const float* b1  = (const float*)d_in[5];
    const float* wl  = (const float*)d_in[6];
    const float* bl  = (const float*)d_in[7];
    float* out = (float*)d_out;

    const int n = in_sizes[0] / H;       // 100000
    const int e = in_sizes[1] / 2;       // 1600000
    const int* src = ei;
    const int* dst = ei + e;

    float *dinv, *lin, *agg, *h0, *csr_w;
    int *cnt, *rowstart, *cursor, *bsum, *csr_src;
    cudaGetSymbolAddress((void**)&dinv,     g_dinv);
    cudaGetSymbolAddress((void**)&cnt,      g_cnt);
    cudaGetSymbolAddress((void**)&rowstart, g_rowstart);
    cudaGetSymbolAddress((void**)&cursor,   g_cursor);
    cudaGetSymbolAddress((void**)&bsum,     g_bsum);
    cudaGetSymbolAddress((void**)&csr_src,  g_csr_src);
    cudaGetSymbolAddress((void**)&csr_w,    g_csr_w);
    cudaGetSymbolAddress((void**)&lin,      g_lin);
    cudaGetSymbolAddress((void**)&agg,      g_agg);
    cudaGetSymbolAddress((void**)&h0,       g_h0);

    const int TB = 256;
    const int nb = (n + SEG - 1) / SEG;          // scan blocks (196)

    // ---- CSR build ----
    k_zero_int<<<(n + TB - 1) / TB, TB>>>(cnt, n);
    k_count   <<<(e + TB - 1) / TB, TB>>>(dst, cnt, e);
    k_dinv    <<<(n + TB - 1) / TB, TB>>>(cnt, dinv, n);
    k_scan1   <<<nb, SEG>>>(cnt, rowstart, bsum, n);
    k_scan2   <<<1, 256>>>(bsum, rowstart, nb, n);
    k_scan3   <<<(n + TB - 1) / TB, TB>>>(rowstart, bsum, cursor, n);
    k_scatter <<<(e + TB - 1) / TB, TB>>>(src, dst, dinv, cursor, csr_src, csr_w, e);

    const int gemmBlocks   = (n + 63) / 64;
    const int gatherBlocks = (n * 32 + TB - 1) / TB;   // warp per node

    // ---- layer 0 ----
    k_gemm128<<<gemmBlocks, TB>>>(x, w0, lin, n);
    k_gather <<<gatherBlocks, TB>>>(lin, dinv, rowstart, csr_src, csr_w,
                                    b0, nullptr, h0, n);
    // ---- layer 1 (+ residual) ----
    k_gemm128<<<gemmBlocks, TB>>>(h0, w1, lin, n);
    k_gather <<<gatherBlocks, TB>>>(lin, dinv, rowstart, csr_src, csr_w,
                                    b1, h0, agg, n);
    // ---- classifier ----
    k_cls<<<(n + 7) / 8, TB>>>(agg, wl, bl, out, n);
}

// round 3
// speedup vs baseline: 3.8119x; 1.9005x over previous
#include <cuda_runtime.h>
#include <math.h>

#define NMAX 100000
#define EMAX 1600000
#define H 128
#define C 40
#define SEG 512

typedef unsigned long long ULL;

// ---------------- scratch -------------------------------------------------
__device__ float g_dinv[NMAX];
__device__ int   g_cnt[NMAX];
__device__ int   g_rowstart[NMAX + 1];
__device__ int   g_cursor[NMAX];
__device__ int   g_bsum[(NMAX + SEG - 1) / SEG];
__device__ int   g_csr_src[EMAX];
__device__ float g_csr_w[EMAX];
__device__ float g_lin[(size_t)NMAX * H];
__device__ float g_agg[(size_t)NMAX * H];
__device__ float g_h0 [(size_t)NMAX * H];

// ---------------- f32x2 helpers -------------------------------------------
__device__ __forceinline__ ULL ffma2(ULL a, ULL b, ULL c) {
    ULL d;
    asm("fma.rn.f32x2 %0, %1, %2, %3;" : "=l"(d) : "l"(a), "l"(b), "l"(c));
    return d;
}
__device__ __forceinline__ ULL fdup(float x) {
    ULL r;
    asm("mov.b64 %0, {%1, %1};" : "=l"(r) : "f"(x));
    return r;
}

// ---------------- CSR build ------------------------------------------------
__global__ void k_zero_int(int* p, int n) {
    int i = blockIdx.x * blockDim.x + threadIdx.x;
    if (i < n) p[i] = 0;
}
__global__ void k_count(const int* __restrict__ dst, int* cnt, int e) {
    int i = blockIdx.x * blockDim.x + threadIdx.x;
    if (i < e) atomicAdd(&cnt[dst[i]], 1);
}
__global__ void k_dinv(const int* __restrict__ cnt, float* dinv, int n) {
    int i = blockIdx.x * blockDim.x + threadIdx.x;
    if (i < n) dinv[i] = rsqrtf((float)(cnt[i] + 1));
}
__global__ void k_scan1(const int* __restrict__ cnt, int* rowstart, int* bsum, int n) {
    __shared__ int sh[SEG];
    int i = blockIdx.x * SEG + threadIdx.x;
    int v = (i < n) ? cnt[i] : 0;
    sh[threadIdx.x] = v;
    __syncthreads();
#pragma unroll
    for (int o = 1; o < SEG; o <<= 1) {
        int t = (threadIdx.x >= o) ? sh[threadIdx.x - o] : 0;
        __syncthreads();
        sh[threadIdx.x] += t;
        __syncthreads();
    }
    if (i < n) rowstart[i] = sh[threadIdx.x] - v;
    if (threadIdx.x == SEG - 1) bsum[blockIdx.x] = sh[SEG - 1];
}
__global__ void k_scan2(int* bsum, int* rowstart, int nb, int n) {
    __shared__ int sh[256];
    int v = (threadIdx.x < nb) ? bsum[threadIdx.x] : 0;
    sh[threadIdx.x] = v;
    __syncthreads();
#pragma unroll
    for (int o = 1; o < 256; o <<= 1) {
        int t = (threadIdx.x >= o) ? sh[threadIdx.x - o] : 0;
        __syncthreads();
        sh[threadIdx.x] += t;
        __syncthreads();
    }
    if (threadIdx.x < nb) bsum[threadIdx.x] = sh[threadIdx.x] - v;
    if (threadIdx.x == 255) rowstart[n] = sh[255];
}
__global__ void k_scan3(int* rowstart, const int* __restrict__ bsum, int* cursor, int n) {
    int i = blockIdx.x * blockDim.x + threadIdx.x;
    if (i < n) {
        int r = rowstart[i] + bsum[i / SEG];
        rowstart[i] = r;
        cursor[i]   = r;
    }
}
__global__ void k_scatter(const int* __restrict__ src, const int* __restrict__ dst,
                          const float* __restrict__ dinv, int* cursor,
                          int* csr_src, float* csr_w, int e) {
    int i = blockIdx.x * blockDim.x + threadIdx.x;
    if (i >= e) return;
    int s = src[i], d = dst[i];
    int p = atomicAdd(&cursor[d], 1);
    csr_src[p] = s;
    csr_w[p]   = dinv[s] * dinv[d];
}

// ---------------------------------------------------------------------------
// GEMM: C[M,128] = A[M,128] @ B[128,128]  (fp32, packed f32x2 FMA)
// BM=64 BN=128 BK=32, 256 threads, thread tile 8 rows x 4 cols (row-paired)
// ---------------------------------------------------------------------------
__global__ void k_gemm128(const float* __restrict__ A,
                          const float* __restrict__ B,
                          float* __restrict__ Cm, int M) {
    __shared__ float AsT[32][66];    // transposed: [k][row], pad keeps 8B align
    __shared__ float Bs[32][128];

    const int tx = threadIdx.x & 31;
    const int ty = threadIdx.x >> 5;
    const int rowBase = blockIdx.x * 64;

    ULL acc[4][4];                   // [row-pair][col], each = 2 rows packed
#pragma unroll
    for (int i = 0; i < 4; i++)
#pragma unroll
        for (int j = 0; j < 4; j++) acc[i][j] = 0ull;

    const int r  = threadIdx.x >> 2;
    const int c4 = (threadIdx.x & 3) << 2;
    const int gr = rowBase + r;

    for (int k0 = 0; k0 < 128; k0 += 32) {
        // A tile -> transposed smem
#pragma unroll
        for (int hh = 0; hh < 2; hh++) {
            int c = c4 + hh * 16;
            float4 v = make_float4(0.f, 0.f, 0.f, 0.f);
            if (gr < M) v = *(const float4*)(A + (size_t)gr * 128 + k0 + c);
            AsT[c + 0][r] = v.x; AsT[c + 1][r] = v.y;
            AsT[c + 2][r] = v.z; AsT[c + 3][r] = v.w;
        }
        // B tile
#pragma unroll
        for (int it = 0; it < 4; it++) {
            int idx = threadIdx.x + it * 256;
            int rr  = idx >> 5;
            int cc  = (idx & 31) << 2;
            *(float4*)&Bs[rr][cc] = *(const float4*)(B + (size_t)(k0 + rr) * 128 + cc);
        }
        __syncthreads();

#pragma unroll 8
        for (int kk = 0; kk < 32; kk++) {
            ULL a0 = *(const ULL*)&AsT[kk][ty * 8 + 0];
            ULL a1 = *(const ULL*)&AsT[kk][ty * 8 + 2];
            ULL a2 = *(const ULL*)&AsT[kk][ty * 8 + 4];
            ULL a3 = *(const ULL*)&AsT[kk][ty * 8 + 6];
            float4 bq = *(const float4*)&Bs[kk][tx << 2];
            ULL b0 = fdup(bq.x), b1 = fdup(bq.y), b2 = fdup(bq.z), b3 = fdup(bq.w);
            acc[0][0] = ffma2(a0, b0, acc[0][0]);
            acc[0][1] = ffma2(a0, b1, acc[0][1]);
            acc[0][2] = ffma2(a0, b2, acc[0][2]);
            acc[0][3] = ffma2(a0, b3, acc[0][3]);
            acc[1][0] = ffma2(a1, b0, acc[1][0]);
            acc[1][1] = ffma2(a1, b1, acc[1][1]);
            acc[1][2] = ffma2(a1, b2, acc[1][2]);
            acc[1][3] = ffma2(a1, b3, acc[1][3]);
            acc[2][0] = ffma2(a2, b0, acc[2][0]);
            acc[2][1] = ffma2(a2, b1, acc[2][1]);
            acc[2][2] = ffma2(a2, b2, acc[2][2]);
            acc[2][3] = ffma2(a2, b3, acc[2][3]);
            acc[3][0] = ffma2(a3, b0, acc[3][0]);
            acc[3][1] = ffma2(a3, b1, acc[3][1]);
            acc[3][2] = ffma2(a3, b2, acc[3][2]);
            acc[3][3] = ffma2(a3, b3, acc[3][3]);
        }
        __syncthreads();
    }

#pragma unroll
    for (int i = 0; i < 4; i++) {
        float2 p0 = *(float2*)&acc[i][0];
        float2 p1 = *(float2*)&acc[i][1];
        float2 p2 = *(float2*)&acc[i][2];
        float2 p3 = *(float2*)&acc[i][3];
        int r0 = rowBase + ty * 8 + 2 * i;
        if (r0 < M)
            *(float4*)(Cm + (size_t)r0 * 128 + (tx << 2)) =
                make_float4(p0.x, p1.x, p2.x, p3.x);
        if (r0 + 1 < M)
            *(float4*)(Cm + (size_t)(r0 + 1) * 128 + (tx << 2)) =
                make_float4(p0.y, p1.y, p2.y, p3.y);
    }
}

// ---------------------------------------------------------------------------
// fused gather (warp per dst node, unroll 4):
//   acc = dinv^2*lin[v] + sum w*lin[src];  out = relu(acc+b) [+res]
// ---------------------------------------------------------------------------
__global__ void k_gather(const float* __restrict__ lin,
                         const float* __restrict__ dinv,
                         const int* __restrict__ rowstart,
                         const int* __restrict__ csr_src,
                         const float* __restrict__ csr_w,
                         const float* __restrict__ bias,
                         const float* __restrict__ res,
                         float* __restrict__ out, int n) {
    int v = (blockIdx.x * blockDim.x + threadIdx.x) >> 5;
    int lane = threadIdx.x & 31;
    if (v >= n) return;

    int beg = rowstart[v];
    int end = rowstart[v + 1];
    float dv = dinv[v];
    float sl = dv * dv;

    float4 acc = *(const float4*)(lin + (size_t)v * 128 + (lane << 2));
    acc.x *= sl; acc.y *= sl; acc.z *= sl; acc.w *= sl;

    int i = beg;
    for (; i + 3 < end; i += 4) {
        int   s0 = csr_src[i],     s1 = csr_src[i + 1];
        int   s2 = csr_src[i + 2], s3 = csr_src[i + 3];
        float w0 = csr_w[i],       w1 = csr_w[i + 1];
        float w2 = csr_w[i + 2],   w3 = csr_w[i + 3];
        float4 x0 = *(const float4*)(lin + (size_t)s0 * 128 + (lane << 2));
        float4 x1 = *(const float4*)(lin + (size_t)s1 * 128 + (lane << 2));
        float4 x2 = *(const float4*)(lin + (size_t)s2 * 128 + (lane << 2));
        float4 x3 = *(const float4*)(lin + (size_t)s3 * 128 + (lane << 2));
        acc.x = fmaf(w0, x0.x, acc.x); acc.y = fmaf(w0, x0.y, acc.y);
        acc.z = fmaf(w0, x0.z, acc.z); acc.w = fmaf(w0, x0.w, acc.w);
        acc.x = fmaf(w1, x1.x, acc.x); acc.y = fmaf(w1, x1.y, acc.y);
        acc.z = fmaf(w1, x1.z, acc.z); acc.w = fmaf(w1, x1.w, acc.w);
        acc.x = fmaf(w2, x2.x, acc.x); acc.y = fmaf(w2, x2.y, acc.y);
        acc.z = fmaf(w2, x2.z, acc.z); acc.w = fmaf(w2, x2.w, acc.w);
        acc.x = fmaf(w3, x3.x, acc.x); acc.y = fmaf(w3, x3.y, acc.y);
        acc.z = fmaf(w3, x3.z, acc.z); acc.w = fmaf(w3, x3.w, acc.w);
    }
    for (; i < end; i++) {
        int   s0 = csr_src[i];
        float w0 = csr_w[i];
        float4 x0 = *(const float4*)(lin + (size_t)s0 * 128 + (lane << 2));
        acc.x = fmaf(w0, x0.x, acc.x); acc.y = fmaf(w0, x0.y, acc.y);
        acc.z = fmaf(w0, x0.z, acc.z); acc.w = fmaf(w0, x0.w, acc.w);
    }

    float4 bb = ((const float4*)bias)[lane];
    acc.x = fmaxf(acc.x + bb.x, 0.f);
    acc.y = fmaxf(acc.y + bb.y, 0.f);
    acc.z = fmaxf(acc.z + bb.z, 0.f);
    acc.w = fmaxf(acc.w + bb.w, 0.f);
    if (res) {
        float4 rr = *(const float4*)(res + (size_t)v * 128 + (lane << 2));
        acc.x += rr.x; acc.y += rr.y; acc.z += rr.z; acc.w += rr.w;
    }
    *(float4*)(out + (size_t)v * 128 + (lane << 2)) = acc;
}

// ---------------------------------------------------------------------------
// classifier GEMM: out[N,40] = h[N,128] @ wl[128,40] + bl  (packed f32x2)
// BM=256, BK=16, 256 threads, thread tile 8 rows x 5 cols (row-paired)
// ---------------------------------------------------------------------------
__global__ void k_cls_gemm(const float* __restrict__ h,
                           const float* __restrict__ wl,
                           const float* __restrict__ bl,
                           float* __restrict__ out, int n) {
    __shared__ float AsT[16][258];   // [k][row], 258 keeps 8B align + low conflict
    __shared__ float Bsf[16 * C];
    __shared__ float sbl[C];

    const int tx = threadIdx.x & 7;   // 8 col groups x 5 cols
    const int ty = threadIdx.x >> 3;  // 32 row groups x 8 rows
    const int rowBase = blockIdx.x * 256;

    if (threadIdx.x < C) sbl[threadIdx.x] = bl[threadIdx.x];

    ULL acc[4][5];
#pragma unroll
    for (int i = 0; i < 4; i++)
#pragma unroll
        for (int j = 0; j < 5; j++) acc[i][j] = 0ull;

    const int gr = rowBase + threadIdx.x;

    for (int k0 = 0; k0 < 128; k0 += 16) {
#pragma unroll
        for (int i = 0; i < 4; i++) {
            float4 v = make_float4(0.f, 0.f, 0.f, 0.f);
            if (gr < n) v = *(const float4*)(h + (size_t)gr * 128 + k0 + i * 4);
            AsT[i * 4 + 0][threadIdx.x] = v.x;
            AsT[i * 4 + 1][threadIdx.x] = v.y;
            AsT[i * 4 + 2][threadIdx.x] = v.z;
            AsT[i * 4 + 3][threadIdx.x] = v.w;
        }
        for (int i = threadIdx.x; i < 16 * C; i += 256)
            Bsf[i] = wl[k0 * C + i];
        __syncthreads();

#pragma unroll 4
        for (int kk = 0; kk < 16; kk++) {
            ULL a0 = *(const ULL*)&AsT[kk][ty * 8 + 0];
            ULL a1 = *(const ULL*)&AsT[kk][ty * 8 + 2];
            ULL a2 = *(const ULL*)&AsT[kk][ty * 8 + 4];
            ULL a3 = *(const ULL*)&AsT[kk][ty * 8 + 6];
            const float* bp = &Bsf[kk * C + tx * 5];
            ULL b0 = fdup(bp[0]), b1 = fdup(bp[1]), b2 = fdup(bp[2]);
            ULL b3 = fdup(bp[3]), b4 = fdup(bp[4]);
#define CLS_ROW(i, ai) \
            acc[i][0] = ffma2(ai, b0, acc[i][0]); \
            acc[i][1] = ffma2(ai, b1, acc[i][1]); \
            acc[i][2] = ffma2(ai, b2, acc[i][2]); \
            acc[i][3] = ffma2(ai, b3, acc[i][3]); \
            acc[i][4] = ffma2(ai, b4, acc[i][4]);
            CLS_ROW(0, a0) CLS_ROW(1, a1) CLS_ROW(2, a2) CLS_ROW(3, a3)
#undef CLS_ROW
        }
        __syncthreads();
    }

#pragma unroll
    for (int i = 0; i < 4; i++) {
        int r0 = rowBase + ty * 8 + 2 * i;
#pragma unroll
        for (int j = 0; j < 5; j++) {
            float2 u = *(float2*)&acc[i][j];
            int col = tx * 5 + j;
            if (r0 < n)     out[(size_t)r0 * C + col]       = u.x + sbl[col];
            if (r0 + 1 < n) out[(size_t)(r0 + 1) * C + col] = u.y + sbl[col];
        }
    }
}

// ---------------------------------------------------------------------------
// in-place log_softmax over 40 classes: warp per row
// ---------------------------------------------------------------------------
__global__ void k_lsm(float* out, int n) {
    int v = (blockIdx.x * blockDim.x + threadIdx.x) >> 5;
    int lane = threadIdx.x & 31;
    if (v >= n) return;
    float* row = out + (size_t)v * C;
    float l0 = row[lane];
    float l1 = (lane < C - 32) ? row[32 + lane] : -1e30f;
    float m = fmaxf(l0, l1);
#pragma unroll
    for (int o = 16; o; o >>= 1) m = fmaxf(m, __shfl_xor_sync(0xffffffffu, m, o));
    float se = __expf(l0 - m) + ((lane < C - 32) ? __expf(l1 - m) : 0.f);
#pragma unroll
    for (int o = 16; o; o >>= 1) se += __shfl_xor_sync(0xffffffffu, se, o);
    float lse = __logf(se) + m;
    row[lane] = l0 - lse;
    if (lane < C - 32) row[32 + lane] = l1 - lse;
}

// ---------------------------------------------------------------------------
// launch
// ---------------------------------------------------------------------------
extern "C" void kernel_launch(void* const* d_in, const int* in_sizes, int n_in,
                              void* d_out, int out_size) {
    const float* x   = (const float*)d_in[0];
    const int*   ei  = (const int*)d_in[1];
    const float* w0  = (const float*)d_in[2];
    const float* b0  = (const float*)d_in[3];
    const float* w1  = (const float*)d_in[4];
    const float* b1  = (const float*)d_in[5];
    const float* wl  = (const float*)d_in[6];
    const float* bl  = (const float*)d_in[7];
    float* out = (float*)d_out;

    const int n = in_sizes[0] / H;
    const int e = in_sizes[1] / 2;
    const int* src = ei;
    const int* dst = ei + e;

    float *dinv, *lin, *agg, *h0, *csr_w;
    int *cnt, *rowstart, *cursor, *bsum, *csr_src;
    cudaGetSymbolAddress((void**)&dinv,     g_dinv);
    cudaGetSymbolAddress((void**)&cnt,      g_cnt);
    cudaGetSymbolAddress((void**)&rowstart, g_rowstart);
    cudaGetSymbolAddress((void**)&cursor,   g_cursor);
    cudaGetSymbolAddress((void**)&bsum,     g_bsum);
    cudaGetSymbolAddress((void**)&csr_src,  g_csr_src);
    cudaGetSymbolAddress((void**)&csr_w,    g_csr_w);
    cudaGetSymbolAddress((void**)&lin,      g_lin);
    cudaGetSymbolAddress((void**)&agg,      g_agg);
    cudaGetSymbolAddress((void**)&h0,       g_h0);

    const int TB = 256;
    const int nb = (n + SEG - 1) / SEG;

    k_zero_int<<<(n + TB - 1) / TB, TB>>>(cnt, n);
    k_count   <<<(e + TB - 1) / TB, TB>>>(dst, cnt, e);
    k_dinv    <<<(n + TB - 1) / TB, TB>>>(cnt, dinv, n);
    k_scan1   <<<nb, SEG>>>(cnt, rowstart, bsum, n);
    k_scan2   <<<1, 256>>>(bsum, rowstart, nb, n);
    k_scan3   <<<(n + TB - 1) / TB, TB>>>(rowstart, bsum, cursor, n);
    k_scatter <<<(e + TB - 1) / TB, TB>>>(src, dst, dinv, cursor, csr_src, csr_w, e);

    const int gemmBlocks   = (n + 63) / 64;
    const int gatherBlocks = (n * 32 + TB - 1) / TB;

    k_gemm128<<<gemmBlocks, TB>>>(x, w0, lin, n);
    k_gather <<<gatherBlocks, TB>>>(lin, dinv, rowstart, csr_src, csr_w,
                                    b0, nullptr, h0, n);
    k_gemm128<<<gemmBlocks, TB>>>(h0, w1, lin, n);
    k_gather <<<gatherBlocks, TB>>>(lin, dinv, rowstart, csr_src, csr_w,
                                    b1, h0, agg, n);

    k_cls_gemm<<<(n + 255) / 256, TB>>>(agg, wl, bl, out, n);
    k_lsm     <<<(n * 32 + TB - 1) / TB, TB>>>(out, n);
}

// round 4
// speedup vs baseline: 4.2503x; 1.1150x over previous
#include <cuda_runtime.h>
#include <math.h>

#define NMAX 100000
#define EMAX 1600000
#define H 128
#define C 40
#define SEG 512

typedef unsigned long long ULL;

// ---------------- scratch -------------------------------------------------
__device__ float g_dinv[NMAX];
__device__ int   g_cnt[NMAX];
__device__ int   g_rowstart[NMAX + 1];
__device__ int   g_cursor[NMAX];
__device__ int   g_bsum[(NMAX + SEG - 1) / SEG];
__device__ int   g_csr_src[EMAX];
__device__ float g_csr_w[EMAX];
__device__ float g_lin[(size_t)NMAX * H];
__device__ float g_agg[(size_t)NMAX * H];
__device__ float g_h0 [(size_t)NMAX * H];

// ---------------- f32x2 helpers -------------------------------------------
__device__ __forceinline__ ULL ffma2(ULL a, ULL b, ULL c) {
    ULL d;
    asm("fma.rn.f32x2 %0, %1, %2, %3;" : "=l"(d) : "l"(a), "l"(b), "l"(c));
    return d;
}
__device__ __forceinline__ ULL fdup(float x) {
    ULL r;
    asm("mov.b64 %0, {%1, %1};" : "=l"(r) : "f"(x));
    return r;
}

// ---------------- CSR build ------------------------------------------------
__global__ void k_count(const int* __restrict__ dst, int* cnt, int e) {
    int i = blockIdx.x * blockDim.x + threadIdx.x;
    if (i < e) atomicAdd(&cnt[dst[i]], 1);
}
__global__ void k_dinv(const int* __restrict__ cnt, float* dinv, int n) {
    int i = blockIdx.x * blockDim.x + threadIdx.x;
    if (i < n) dinv[i] = rsqrtf((float)(cnt[i] + 1));
}
__global__ void k_scan1(const int* __restrict__ cnt, int* rowstart, int* bsum, int n) {
    __shared__ int sh[SEG];
    int i = blockIdx.x * SEG + threadIdx.x;
    int v = (i < n) ? cnt[i] : 0;
    sh[threadIdx.x] = v;
    __syncthreads();
#pragma unroll
    for (int o = 1; o < SEG; o <<= 1) {
        int t = (threadIdx.x >= o) ? sh[threadIdx.x - o] : 0;
        __syncthreads();
        sh[threadIdx.x] += t;
        __syncthreads();
    }
    if (i < n) rowstart[i] = sh[threadIdx.x] - v;
    if (threadIdx.x == SEG - 1) bsum[blockIdx.x] = sh[SEG - 1];
}
__global__ void k_scan2(int* bsum, int* rowstart, int nb, int n) {
    __shared__ int sh[256];
    int v = (threadIdx.x < nb) ? bsum[threadIdx.x] : 0;
    sh[threadIdx.x] = v;
    __syncthreads();
#pragma unroll
    for (int o = 1; o < 256; o <<= 1) {
        int t = (threadIdx.x >= o) ? sh[threadIdx.x - o] : 0;
        __syncthreads();
        sh[threadIdx.x] += t;
        __syncthreads();
    }
    if (threadIdx.x < nb) bsum[threadIdx.x] = sh[threadIdx.x] - v;
    if (threadIdx.x == 255) rowstart[n] = sh[255];
}
__global__ void k_scan3(int* rowstart, const int* __restrict__ bsum, int* cursor, int n) {
    int i = blockIdx.x * blockDim.x + threadIdx.x;
    if (i < n) {
        int r = rowstart[i] + bsum[i / SEG];
        rowstart[i] = r;
        cursor[i]   = r;
    }
}
__global__ void k_scatter(const int* __restrict__ src, const int* __restrict__ dst,
                          const float* __restrict__ dinv, int* cursor,
                          int* csr_src, float* csr_w, int e) {
    int i = blockIdx.x * blockDim.x + threadIdx.x;
    if (i >= e) return;
    int s = src[i], d = dst[i];
    int p = atomicAdd(&cursor[d], 1);
    csr_src[p] = s;
    csr_w[p]   = dinv[s] * dinv[d];
}

// ---------------------------------------------------------------------------
// GEMM: C[M,128] = A[M,128] @ B[128,128]  (fp32, packed f32x2 FMA)
// ---------------------------------------------------------------------------
__global__ void k_gemm128(const float* __restrict__ A,
                          const float* __restrict__ B,
                          float* __restrict__ Cm, int M) {
    __shared__ float AsT[32][66];
    __shared__ float Bs[32][128];

    const int tx = threadIdx.x & 31;
    const int ty = threadIdx.x >> 5;
    const int rowBase = blockIdx.x * 64;

    ULL acc[4][4];
#pragma unroll
    for (int i = 0; i < 4; i++)
#pragma unroll
        for (int j = 0; j < 4; j++) acc[i][j] = 0ull;

    const int r  = threadIdx.x >> 2;
    const int c4 = (threadIdx.x & 3) << 2;
    const int gr = rowBase + r;

    for (int k0 = 0; k0 < 128; k0 += 32) {
#pragma unroll
        for (int hh = 0; hh < 2; hh++) {
            int c = c4 + hh * 16;
            float4 v = make_float4(0.f, 0.f, 0.f, 0.f);
            if (gr < M) v = *(const float4*)(A + (size_t)gr * 128 + k0 + c);
            AsT[c + 0][r] = v.x; AsT[c + 1][r] = v.y;
            AsT[c + 2][r] = v.z; AsT[c + 3][r] = v.w;
        }
#pragma unroll
        for (int it = 0; it < 4; it++) {
            int idx = threadIdx.x + it * 256;
            int rr  = idx >> 5;
            int cc  = (idx & 31) << 2;
            *(float4*)&Bs[rr][cc] = *(const float4*)(B + (size_t)(k0 + rr) * 128 + cc);
        }
        __syncthreads();

#pragma unroll 8
        for (int kk = 0; kk < 32; kk++) {
            ULL a0 = *(const ULL*)&AsT[kk][ty * 8 + 0];
            ULL a1 = *(const ULL*)&AsT[kk][ty * 8 + 2];
            ULL a2 = *(const ULL*)&AsT[kk][ty * 8 + 4];
            ULL a3 = *(const ULL*)&AsT[kk][ty * 8 + 6];
            float4 bq = *(const float4*)&Bs[kk][tx << 2];
            ULL b0 = fdup(bq.x), b1 = fdup(bq.y), b2 = fdup(bq.z), b3 = fdup(bq.w);
            acc[0][0] = ffma2(a0, b0, acc[0][0]);
            acc[0][1] = ffma2(a0, b1, acc[0][1]);
            acc[0][2] = ffma2(a0, b2, acc[0][2]);
            acc[0][3] = ffma2(a0, b3, acc[0][3]);
            acc[1][0] = ffma2(a1, b0, acc[1][0]);
            acc[1][1] = ffma2(a1, b1, acc[1][1]);
            acc[1][2] = ffma2(a1, b2, acc[1][2]);
            acc[1][3] = ffma2(a1, b3, acc[1][3]);
            acc[2][0] = ffma2(a2, b0, acc[2][0]);
            acc[2][1] = ffma2(a2, b1, acc[2][1]);
            acc[2][2] = ffma2(a2, b2, acc[2][2]);
            acc[2][3] = ffma2(a2, b3, acc[2][3]);
            acc[3][0] = ffma2(a3, b0, acc[3][0]);
            acc[3][1] = ffma2(a3, b1, acc[3][1]);
            acc[3][2] = ffma2(a3, b2, acc[3][2]);
            acc[3][3] = ffma2(a3, b3, acc[3][3]);
        }
        __syncthreads();
    }

#pragma unroll
    for (int i = 0; i < 4; i++) {
        float2 p0 = *(float2*)&acc[i][0];
        float2 p1 = *(float2*)&acc[i][1];
        float2 p2 = *(float2*)&acc[i][2];
        float2 p3 = *(float2*)&acc[i][3];
        int r0 = rowBase + ty * 8 + 2 * i;
        if (r0 < M)
            *(float4*)(Cm + (size_t)r0 * 128 + (tx << 2)) =
                make_float4(p0.x, p1.x, p2.x, p3.x);
        if (r0 + 1 < M)
            *(float4*)(Cm + (size_t)(r0 + 1) * 128 + (tx << 2)) =
                make_float4(p0.y, p1.y, p2.y, p3.y);
    }
}

// ---------------------------------------------------------------------------
// fused gather (warp per dst node, unroll 4)
// ---------------------------------------------------------------------------
__global__ void k_gather(const float* __restrict__ lin,
                         const float* __restrict__ dinv,
                         const int* __restrict__ rowstart,
                         const int* __restrict__ csr_src,
                         const float* __restrict__ csr_w,
                         const float* __restrict__ bias,
                         const float* __restrict__ res,
                         float* __restrict__ out, int n) {
    int v = (blockIdx.x * blockDim.x + threadIdx.x) >> 5;
    int lane = threadIdx.x & 31;
    if (v >= n) return;

    int beg = rowstart[v];
    int end = rowstart[v + 1];
    float dv = dinv[v];
    float sl = dv * dv;

    float4 acc = *(const float4*)(lin + (size_t)v * 128 + (lane << 2));
    acc.x *= sl; acc.y *= sl; acc.z *= sl; acc.w *= sl;

    int i = beg;
    for (; i + 3 < end; i += 4) {
        int   s0 = csr_src[i],     s1 = csr_src[i + 1];
        int   s2 = csr_src[i + 2], s3 = csr_src[i + 3];
        float w0 = csr_w[i],       w1 = csr_w[i + 1];
        float w2 = csr_w[i + 2],   w3 = csr_w[i + 3];
        float4 x0 = *(const float4*)(lin + (size_t)s0 * 128 + (lane << 2));
        float4 x1 = *(const float4*)(lin + (size_t)s1 * 128 + (lane << 2));
        float4 x2 = *(const float4*)(lin + (size_t)s2 * 128 + (lane << 2));
        float4 x3 = *(const float4*)(lin + (size_t)s3 * 128 + (lane << 2));
        acc.x = fmaf(w0, x0.x, acc.x); acc.y = fmaf(w0, x0.y, acc.y);
        acc.z = fmaf(w0, x0.z, acc.z); acc.w = fmaf(w0, x0.w, acc.w);
        acc.x = fmaf(w1, x1.x, acc.x); acc.y = fmaf(w1, x1.y, acc.y);
        acc.z = fmaf(w1, x1.z, acc.z); acc.w = fmaf(w1, x1.w, acc.w);
        acc.x = fmaf(w2, x2.x, acc.x); acc.y = fmaf(w2, x2.y, acc.y);
        acc.z = fmaf(w2, x2.z, acc.z); acc.w = fmaf(w2, x2.w, acc.w);
        acc.x = fmaf(w3, x3.x, acc.x); acc.y = fmaf(w3, x3.y, acc.y);
        acc.z = fmaf(w3, x3.z, acc.z); acc.w = fmaf(w3, x3.w, acc.w);
    }
    for (; i < end; i++) {
        int   s0 = csr_src[i];
        float w0 = csr_w[i];
        float4 x0 = *(const float4*)(lin + (size_t)s0 * 128 + (lane << 2));
        acc.x = fmaf(w0, x0.x, acc.x); acc.y = fmaf(w0, x0.y, acc.y);
        acc.z = fmaf(w0, x0.z, acc.z); acc.w = fmaf(w0, x0.w, acc.w);
    }

    float4 bb = ((const float4*)bias)[lane];
    acc.x = fmaxf(acc.x + bb.x, 0.f);
    acc.y = fmaxf(acc.y + bb.y, 0.f);
    acc.z = fmaxf(acc.z + bb.z, 0.f);
    acc.w = fmaxf(acc.w + bb.w, 0.f);
    if (res) {
        float4 rr = *(const float4*)(res + (size_t)v * 128 + (lane << 2));
        acc.x += rr.x; acc.y += rr.y; acc.z += rr.z; acc.w += rr.w;
    }
    *(float4*)(out + (size_t)v * 128 + (lane << 2)) = acc;
}

// ---------------------------------------------------------------------------
// classifier GEMM + fused log_softmax:
// out[N,40] = log_softmax(h[N,128] @ wl[128,40] + bl)
// BM=256, BK=16, 256 threads, thread tile 8 rows x 5 cols; each row's 40
// logits live in 8 consecutive lanes -> shfl_xor(1,2,4) group reduce.
// ---------------------------------------------------------------------------
__global__ void k_cls_gemm(const float* __restrict__ h,
                           const float* __restrict__ wl,
                           const float* __restrict__ bl,
                           float* __restrict__ out, int n) {
    __shared__ float AsT[16][258];
    __shared__ float Bsf[16 * C];
    __shared__ float sbl[C];

    const int tx = threadIdx.x & 7;
    const int ty = threadIdx.x >> 3;
    const int rowBase = blockIdx.x * 256;

    if (threadIdx.x < C) sbl[threadIdx.x] = bl[threadIdx.x];

    ULL acc[4][5];
#pragma unroll
    for (int i = 0; i < 4; i++)
#pragma unroll
        for (int j = 0; j < 5; j++) acc[i][j] = 0ull;

    const int gr = rowBase + threadIdx.x;

    for (int k0 = 0; k0 < 128; k0 += 16) {
#pragma unroll
        for (int i = 0; i < 4; i++) {
            float4 v = make_float4(0.f, 0.f, 0.f, 0.f);
            if (gr < n) v = *(const float4*)(h + (size_t)gr * 128 + k0 + i * 4);
            AsT[i * 4 + 0][threadIdx.x] = v.x;
            AsT[i * 4 + 1][threadIdx.x] = v.y;
            AsT[i * 4 + 2][threadIdx.x] = v.z;
            AsT[i * 4 + 3][threadIdx.x] = v.w;
        }
        for (int i = threadIdx.x; i < 16 * C; i += 256)
            Bsf[i] = wl[k0 * C + i];
        __syncthreads();

#pragma unroll 4
        for (int kk = 0; kk < 16; kk++) {
            ULL a0 = *(const ULL*)&AsT[kk][ty * 8 + 0];
            ULL a1 = *(const ULL*)&AsT[kk][ty * 8 + 2];
            ULL a2 = *(const ULL*)&AsT[kk][ty * 8 + 4];
            ULL a3 = *(const ULL*)&AsT[kk][ty * 8 + 6];
            const float* bp = &Bsf[kk * C + tx * 5];
            ULL b0 = fdup(bp[0]), b1 = fdup(bp[1]), b2 = fdup(bp[2]);
            ULL b3 = fdup(bp[3]), b4 = fdup(bp[4]);
#define CLS_ROW(i, ai) \
            acc[i][0] = ffma2(ai, b0, acc[i][0]); \
            acc[i][1] = ffma2(ai, b1, acc[i][1]); \
            acc[i][2] = ffma2(ai, b2, acc[i][2]); \
            acc[i][3] = ffma2(ai, b3, acc[i][3]); \
            acc[i][4] = ffma2(ai, b4, acc[i][4]);
            CLS_ROW(0, a0) CLS_ROW(1, a1) CLS_ROW(2, a2) CLS_ROW(3, a3)
#undef CLS_ROW
        }
        __syncthreads();
    }

    // epilogue: bias + log_softmax per row, group of 8 lanes owns a row
    const float bb0 = sbl[tx * 5 + 0], bb1 = sbl[tx * 5 + 1], bb2 = sbl[tx * 5 + 2];
    const float bb3 = sbl[tx * 5 + 3], bb4 = sbl[tx * 5 + 4];

#pragma unroll
    for (int i = 0; i < 4; i++) {
#pragma unroll
        for (int half = 0; half < 2; half++) {
            int r0 = rowBase + ty * 8 + 2 * i + half;
            float v0 = ((float2*)&acc[i][0])[0].x, w0;
            // extract half (x or y) of each packed pair
            float2 q0 = *(float2*)&acc[i][0];
            float2 q1 = *(float2*)&acc[i][1];
            float2 q2 = *(float2*)&acc[i][2];
            float2 q3 = *(float2*)&acc[i][3];
            float2 q4 = *(float2*)&acc[i][4];
            float l0 = (half ? q0.y : q0.x) + bb0;
            float l1 = (half ? q1.y : q1.x) + bb1;
            float l2 = (half ? q2.y : q2.x) + bb2;
            float l3 = (half ? q3.y : q3.x) + bb3;
            float l4 = (half ? q4.y : q4.x) + bb4;

            float m = fmaxf(fmaxf(fmaxf(l0, l1), fmaxf(l2, l3)), l4);
            m = fmaxf(m, __shfl_xor_sync(0xffffffffu, m, 1));
            m = fmaxf(m, __shfl_xor_sync(0xffffffffu, m, 2));
            m = fmaxf(m, __shfl_xor_sync(0xffffffffu, m, 4));
            float se = __expf(l0 - m) + __expf(l1 - m) + __expf(l2 - m)
                     + __expf(l3 - m) + __expf(l4 - m);
            se += __shfl_xor_sync(0xffffffffu, se, 1);
            se += __shfl_xor_sync(0xffffffffu, se, 2);
            se += __shfl_xor_sync(0xffffffffu, se, 4);
            float lse = __logf(se) + m;

            if (r0 < n) {
                float* op = out + (size_t)r0 * C + tx * 5;
                op[0] = l0 - lse; op[1] = l1 - lse; op[2] = l2 - lse;
                op[3] = l3 - lse; op[4] = l4 - lse;
            }
            (void)v0; (void)w0;
        }
    }
}

// ---------------------------------------------------------------------------
// launch  (CSR build forked onto a second stream, joined before gather #0)
// ---------------------------------------------------------------------------
extern "C" void kernel_launch(void* const* d_in, const int* in_sizes, int n_in,
                              void* d_out, int out_size) {
    const float* x   = (const float*)d_in[0];
    const int*   ei  = (const int*)d_in[1];
    const float* w0  = (const float*)d_in[2];
    const float* b0  = (const float*)d_in[3];
    const float* w1  = (const float*)d_in[4];
    const float* b1  = (const float*)d_in[5];
    const float* wl  = (const float*)d_in[6];
    const float* bl  = (const float*)d_in[7];
    float* out = (float*)d_out;

    const int n = in_sizes[0] / H;
    const int e = in_sizes[1] / 2;
    const int* src = ei;
    const int* dst = ei + e;

    float *dinv, *lin, *agg, *h0, *csr_w;
    int *cnt, *rowstart, *cursor, *bsum, *csr_src;
    cudaGetSymbolAddress((void**)&dinv,     g_dinv);
    cudaGetSymbolAddress((void**)&cnt,      g_cnt);
    cudaGetSymbolAddress((void**)&rowstart, g_rowstart);
    cudaGetSymbolAddress((void**)&cursor,   g_cursor);
    cudaGetSymbolAddress((void**)&bsum,     g_bsum);
    cudaGetSymbolAddress((void**)&csr_src,  g_csr_src);
    cudaGetSymbolAddress((void**)&csr_w,    g_csr_w);
    cudaGetSymbolAddress((void**)&lin,      g_lin);
    cudaGetSymbolAddress((void**)&agg,      g_agg);
    cudaGetSymbolAddress((void**)&h0,       g_h0);

    // host-side resources created once (work is identical every call)
    static cudaStream_t s2 = nullptr;
    static cudaEvent_t evFork = nullptr, evJoin = nullptr;
    if (!s2) {
        cudaStreamCreateWithFlags(&s2, cudaStreamNonBlocking);
        cudaEventCreateWithFlags(&evFork, cudaEventDisableTiming);
        cudaEventCreateWithFlags(&evJoin, cudaEventDisableTiming);
    }

    const int TB = 256;
    const int nb = (n + SEG - 1) / SEG;
    const int gemmBlocks   = (n + 63) / 64;
    const int gatherBlocks = (n * 32 + TB - 1) / TB;

    // fork: CSR build on s2, GEMM0 on main stream
    cudaEventRecord(evFork, 0);
    cudaStreamWaitEvent(s2, evFork, 0);

    cudaMemsetAsync(cnt, 0, n * sizeof(int), s2);
    k_count  <<<(e + TB - 1) / TB, TB, 0, s2>>>(dst, cnt, e);
    k_dinv   <<<(n + TB - 1) / TB, TB, 0, s2>>>(cnt, dinv, n);
    k_scan1  <<<nb, SEG, 0, s2>>>(cnt, rowstart, bsum, n);
    k_scan2  <<<1, 256, 0, s2>>>(bsum, rowstart, nb, n);
    k_scan3  <<<(n + TB - 1) / TB, TB, 0, s2>>>(rowstart, bsum, cursor, n);
    k_scatter<<<(e + TB - 1) / TB, TB, 0, s2>>>(src, dst, dinv, cursor,
                                                csr_src, csr_w, e);
    cudaEventRecord(evJoin, s2);

    k_gemm128<<<gemmBlocks, TB>>>(x, w0, lin, n);

    // join: gather #0 needs both lin (main) and CSR (s2)
    cudaStreamWaitEvent(0, evJoin, 0);

    k_gather <<<gatherBlocks, TB>>>(lin, dinv, rowstart, csr_src, csr_w,
                                    b0, nullptr, h0, n);
    k_gemm128<<<gemmBlocks, TB>>>(h0, w1, lin, n);
    k_gather <<<gatherBlocks, TB>>>(lin, dinv, rowstart, csr_src, csr_w,
                                    b1, h0, agg, n);
    k_cls_gemm<<<(n + 255) / 256, TB>>>(agg, wl, bl, out, n);
}

// round 5
// speedup vs baseline: 4.3264x; 1.0179x over previous
#include <cuda_runtime.h>
#include <cuda_bf16.h>
#include <math.h>

#define NMAX 100000
#define EMAX 1600000
#define H 128
#define C 40
#define SEG 512

typedef unsigned long long ULL;

// ---------------- scratch -------------------------------------------------
__device__ float g_dinv[NMAX];
__device__ int   g_cnt[NMAX];
__device__ int   g_rowstart[NMAX + 1];
__device__ int   g_cursor[NMAX];
__device__ int   g_bsum[(NMAX + SEG - 1) / SEG];
__device__ int   g_csr_src[EMAX];
__device__ float g_csr_w[EMAX];
__device__ float g_lin[(size_t)NMAX * H];
__device__ __nv_bfloat16 g_linb[(size_t)NMAX * H];   // bf16 shadow of lin
__device__ float g_agg[(size_t)NMAX * H];
__device__ float g_h0 [(size_t)NMAX * H];

// ---------------- f32x2 helpers -------------------------------------------
__device__ __forceinline__ ULL ffma2(ULL a, ULL b, ULL c) {
    ULL d;
    asm("fma.rn.f32x2 %0, %1, %2, %3;" : "=l"(d) : "l"(a), "l"(b), "l"(c));
    return d;
}
__device__ __forceinline__ ULL fdup(float x) {
    ULL r;
    asm("mov.b64 %0, {%1, %1};" : "=l"(r) : "f"(x));
    return r;
}

// ---------------- CSR build ------------------------------------------------
__global__ void k_count(const int* __restrict__ dst, int* cnt, int e) {
    int i = blockIdx.x * blockDim.x + threadIdx.x;
    if (i < e) atomicAdd(&cnt[dst[i]], 1);
}
__global__ void k_dinv(const int* __restrict__ cnt, float* dinv, int n) {
    int i = blockIdx.x * blockDim.x + threadIdx.x;
    if (i < n) dinv[i] = rsqrtf((float)(cnt[i] + 1));
}
__global__ void k_scan1(const int* __restrict__ cnt, int* rowstart, int* bsum, int n) {
    __shared__ int sh[SEG];
    int i = blockIdx.x * SEG + threadIdx.x;
    int v = (i < n) ? cnt[i] : 0;
    sh[threadIdx.x] = v;
    __syncthreads();
#pragma unroll
    for (int o = 1; o < SEG; o <<= 1) {
        int t = (threadIdx.x >= o) ? sh[threadIdx.x - o] : 0;
        __syncthreads();
        sh[threadIdx.x] += t;
        __syncthreads();
    }
    if (i < n) rowstart[i] = sh[threadIdx.x] - v;
    if (threadIdx.x == SEG - 1) bsum[blockIdx.x] = sh[SEG - 1];
}
__global__ void k_scan2(int* bsum, int* rowstart, int nb, int n) {
    __shared__ int sh[256];
    int v = (threadIdx.x < nb) ? bsum[threadIdx.x] : 0;
    sh[threadIdx.x] = v;
    __syncthreads();
#pragma unroll
    for (int o = 1; o < 256; o <<= 1) {
        int t = (threadIdx.x >= o) ? sh[threadIdx.x - o] : 0;
        __syncthreads();
        sh[threadIdx.x] += t;
        __syncthreads();
    }
    if (threadIdx.x < nb) bsum[threadIdx.x] = sh[threadIdx.x] - v;
    if (threadIdx.x == 255) rowstart[n] = sh[255];
}
__global__ void k_scan3(int* rowstart, const int* __restrict__ bsum, int* cursor, int n) {
    int i = blockIdx.x * blockDim.x + threadIdx.x;
    if (i < n) {
        int r = rowstart[i] + bsum[i / SEG];
        rowstart[i] = r;
        cursor[i]   = r;
    }
}
__global__ void k_scatter(const int* __restrict__ src, const int* __restrict__ dst,
                          const float* __restrict__ dinv, int* cursor,
                          int* csr_src, float* csr_w, int e) {
    int i = blockIdx.x * blockDim.x + threadIdx.x;
    if (i >= e) return;
    int s = src[i], d = dst[i];
    int p = atomicAdd(&cursor[d], 1);
    csr_src[p] = s;
    csr_w[p]   = dinv[s] * dinv[d];
}

// ---------------------------------------------------------------------------
// GEMM: C[M,128] = A[M,128] @ B[128,128]  (fp32, packed f32x2 FMA)
// also emits bf16 shadow copy of C for the gather's neighbor reads
// ---------------------------------------------------------------------------
__global__ void k_gemm128(const float* __restrict__ A,
                          const float* __restrict__ B,
                          float* __restrict__ Cm,
                          __nv_bfloat16* __restrict__ Cb, int M) {
    __shared__ float AsT[32][66];
    __shared__ float Bs[32][128];

    const int tx = threadIdx.x & 31;
    const int ty = threadIdx.x >> 5;
    const int rowBase = blockIdx.x * 64;

    ULL acc[4][4];
#pragma unroll
    for (int i = 0; i < 4; i++)
#pragma unroll
        for (int j = 0; j < 4; j++) acc[i][j] = 0ull;

    const int r  = threadIdx.x >> 2;
    const int c4 = (threadIdx.x & 3) << 2;
    const int gr = rowBase + r;

    for (int k0 = 0; k0 < 128; k0 += 32) {
#pragma unroll
        for (int hh = 0; hh < 2; hh++) {
            int c = c4 + hh * 16;
            float4 v = make_float4(0.f, 0.f, 0.f, 0.f);
            if (gr < M) v = *(const float4*)(A + (size_t)gr * 128 + k0 + c);
            AsT[c + 0][r] = v.x; AsT[c + 1][r] = v.y;
            AsT[c + 2][r] = v.z; AsT[c + 3][r] = v.w;
        }
#pragma unroll
        for (int it = 0; it < 4; it++) {
            int idx = threadIdx.x + it * 256;
            int rr  = idx >> 5;
            int cc  = (idx & 31) << 2;
            *(float4*)&Bs[rr][cc] = *(const float4*)(B + (size_t)(k0 + rr) * 128 + cc);
        }
        __syncthreads();

#pragma unroll 8
        for (int kk = 0; kk < 32; kk++) {
            ULL a0 = *(const ULL*)&AsT[kk][ty * 8 + 0];
            ULL a1 = *(const ULL*)&AsT[kk][ty * 8 + 2];
            ULL a2 = *(const ULL*)&AsT[kk][ty * 8 + 4];
            ULL a3 = *(const ULL*)&AsT[kk][ty * 8 + 6];
            float4 bq = *(const float4*)&Bs[kk][tx << 2];
            ULL b0 = fdup(bq.x), b1 = fdup(bq.y), b2 = fdup(bq.z), b3 = fdup(bq.w);
            acc[0][0] = ffma2(a0, b0, acc[0][0]);
            acc[0][1] = ffma2(a0, b1, acc[0][1]);
            acc[0][2] = ffma2(a0, b2, acc[0][2]);
            acc[0][3] = ffma2(a0, b3, acc[0][3]);
            acc[1][0] = ffma2(a1, b0, acc[1][0]);
            acc[1][1] = ffma2(a1, b1, acc[1][1]);
            acc[1][2] = ffma2(a1, b2, acc[1][2]);
            acc[1][3] = ffma2(a1, b3, acc[1][3]);
            acc[2][0] = ffma2(a2, b0, acc[2][0]);
            acc[2][1] = ffma2(a2, b1, acc[2][1]);
            acc[2][2] = ffma2(a2, b2, acc[2][2]);
            acc[2][3] = ffma2(a2, b3, acc[2][3]);
            acc[3][0] = ffma2(a3, b0, acc[3][0]);
            acc[3][1] = ffma2(a3, b1, acc[3][1]);
            acc[3][2] = ffma2(a3, b2, acc[3][2]);
            acc[3][3] = ffma2(a3, b3, acc[3][3]);
        }
        __syncthreads();
    }

#pragma unroll
    for (int i = 0; i < 4; i++) {
        float2 p0 = *(float2*)&acc[i][0];
        float2 p1 = *(float2*)&acc[i][1];
        float2 p2 = *(float2*)&acc[i][2];
        float2 p3 = *(float2*)&acc[i][3];
        int r0 = rowBase + ty * 8 + 2 * i;
        if (r0 < M) {
            float4 v = make_float4(p0.x, p1.x, p2.x, p3.x);
            *(float4*)(Cm + (size_t)r0 * 128 + (tx << 2)) = v;
            __nv_bfloat162 h0 = __float22bfloat162_rn(make_float2(v.x, v.y));
            __nv_bfloat162 h1 = __float22bfloat162_rn(make_float2(v.z, v.w));
            *(__nv_bfloat162*)(Cb + (size_t)r0 * 128 + (tx << 2))     = h0;
            *(__nv_bfloat162*)(Cb + (size_t)r0 * 128 + (tx << 2) + 2) = h1;
        }
        if (r0 + 1 < M) {
            float4 v = make_float4(p0.y, p1.y, p2.y, p3.y);
            *(float4*)(Cm + (size_t)(r0 + 1) * 128 + (tx << 2)) = v;
            __nv_bfloat162 h0 = __float22bfloat162_rn(make_float2(v.x, v.y));
            __nv_bfloat162 h1 = __float22bfloat162_rn(make_float2(v.z, v.w));
            *(__nv_bfloat162*)(Cb + (size_t)(r0 + 1) * 128 + (tx << 2))     = h0;
            *(__nv_bfloat162*)(Cb + (size_t)(r0 + 1) * 128 + (tx << 2) + 2) = h1;
        }
    }
}

// ---------------------------------------------------------------------------
// fused gather (warp per dst node, unroll 4):
//   neighbor features read from bf16 shadow (half traffic),
//   self-loop / bias / residual / accumulation all fp32
// ---------------------------------------------------------------------------
__device__ __forceinline__ void acc_bf16(float4& acc, float w, ULL packed) {
    __nv_bfloat162 lo = *(__nv_bfloat162*)&packed;
    __nv_bfloat162 hi = *((__nv_bfloat162*)&packed + 1);
    float2 f0 = __bfloat1622float2(lo);
    float2 f1 = __bfloat1622float2(hi);
    acc.x = fmaf(w, f0.x, acc.x);
    acc.y = fmaf(w, f0.y, acc.y);
    acc.z = fmaf(w, f1.x, acc.z);
    acc.w = fmaf(w, f1.y, acc.w);
}

__global__ void k_gather(const float* __restrict__ lin,
                         const __nv_bfloat16* __restrict__ linb,
                         const float* __restrict__ dinv,
                         const int* __restrict__ rowstart,
                         const int* __restrict__ csr_src,
                         const float* __restrict__ csr_w,
                         const float* __restrict__ bias,
                         const float* __restrict__ res,
                         float* __restrict__ out, int n) {
    int v = (blockIdx.x * blockDim.x + threadIdx.x) >> 5;
    int lane = threadIdx.x & 31;
    if (v >= n) return;

    int beg = rowstart[v];
    int end = rowstart[v + 1];
    float dv = dinv[v];
    float sl = dv * dv;

    float4 acc = *(const float4*)(lin + (size_t)v * 128 + (lane << 2));
    acc.x *= sl; acc.y *= sl; acc.z *= sl; acc.w *= sl;

    int i = beg;
    for (; i + 3 < end; i += 4) {
        int   s0 = csr_src[i],     s1 = csr_src[i + 1];
        int   s2 = csr_src[i + 2], s3 = csr_src[i + 3];
        float w0 = csr_w[i],       w1 = csr_w[i + 1];
        float w2 = csr_w[i + 2],   w3 = csr_w[i + 3];
        ULL x0 = *(const ULL*)(linb + (size_t)s0 * 128 + (lane << 2));
        ULL x1 = *(const ULL*)(linb + (size_t)s1 * 128 + (lane << 2));
        ULL x2 = *(const ULL*)(linb + (size_t)s2 * 128 + (lane << 2));
        ULL x3 = *(const ULL*)(linb + (size_t)s3 * 128 + (lane << 2));
        acc_bf16(acc, w0, x0);
        acc_bf16(acc, w1, x1);
        acc_bf16(acc, w2, x2);
        acc_bf16(acc, w3, x3);
    }
    for (; i < end; i++) {
        int   s0 = csr_src[i];
        float w0 = csr_w[i];
        ULL x0 = *(const ULL*)(linb + (size_t)s0 * 128 + (lane << 2));
        acc_bf16(acc, w0, x0);
    }

    float4 bb = ((const float4*)bias)[lane];
    acc.x = fmaxf(acc.x + bb.x, 0.f);
    acc.y = fmaxf(acc.y + bb.y, 0.f);
    acc.z = fmaxf(acc.z + bb.z, 0.f);
    acc.w = fmaxf(acc.w + bb.w, 0.f);
    if (res) {
        float4 rr = *(const float4*)(res + (size_t)v * 128 + (lane << 2));
        acc.x += rr.x; acc.y += rr.y; acc.z += rr.z; acc.w += rr.w;
    }
    *(float4*)(out + (size_t)v * 128 + (lane << 2)) = acc;
}

// ---------------------------------------------------------------------------
// classifier GEMM + fused log_softmax
// ---------------------------------------------------------------------------
__global__ void k_cls_gemm(const float* __restrict__ h,
                           const float* __restrict__ wl,
                           const float* __restrict__ bl,
                           float* __restrict__ out, int n) {
    __shared__ float AsT[16][258];
    __shared__ float Bsf[16 * C];
    __shared__ float sbl[C];

    const int tx = threadIdx.x & 7;
    const int ty = threadIdx.x >> 3;
    const int rowBase = blockIdx.x * 256;

    if (threadIdx.x < C) sbl[threadIdx.x] = bl[threadIdx.x];

    ULL acc[4][5];
#pragma unroll
    for (int i = 0; i < 4; i++)
#pragma unroll
        for (int j = 0; j < 5; j++) acc[i][j] = 0ull;

    const int gr = rowBase + threadIdx.x;

    for (int k0 = 0; k0 < 128; k0 += 16) {
#pragma unroll
        for (int i = 0; i < 4; i++) {
            float4 v = make_float4(0.f, 0.f, 0.f, 0.f);
            if (gr < n) v = *(const float4*)(h + (size_t)gr * 128 + k0 + i * 4);
            AsT[i * 4 + 0][threadIdx.x] = v.x;
            AsT[i * 4 + 1][threadIdx.x] = v.y;
            AsT[i * 4 + 2][threadIdx.x] = v.z;
            AsT[i * 4 + 3][threadIdx.x] = v.w;
        }
        for (int i = threadIdx.x; i < 16 * C; i += 256)
            Bsf[i] = wl[k0 * C + i];
        __syncthreads();

#pragma unroll 4
        for (int kk = 0; kk < 16; kk++) {
            ULL a0 = *(const ULL*)&AsT[kk][ty * 8 + 0];
            ULL a1 = *(const ULL*)&AsT[kk][ty * 8 + 2];
            ULL a2 = *(const ULL*)&AsT[kk][ty * 8 + 4];
            ULL a3 = *(const ULL*)&AsT[kk][ty * 8 + 6];
            const float* bp = &Bsf[kk * C + tx * 5];
            ULL b0 = fdup(bp[0]), b1 = fdup(bp[1]), b2 = fdup(bp[2]);
            ULL b3 = fdup(bp[3]), b4 = fdup(bp[4]);
#define CLS_ROW(i, ai) \
            acc[i][0] = ffma2(ai, b0, acc[i][0]); \
            acc[i][1] = ffma2(ai, b1, acc[i][1]); \
            acc[i][2] = ffma2(ai, b2, acc[i][2]); \
            acc[i][3] = ffma2(ai, b3, acc[i][3]); \
            acc[i][4] = ffma2(ai, b4, acc[i][4]);
            CLS_ROW(0, a0) CLS_ROW(1, a1) CLS_ROW(2, a2) CLS_ROW(3, a3)
#undef CLS_ROW
        }
        __syncthreads();
    }

    const float bb0 = sbl[tx * 5 + 0], bb1 = sbl[tx * 5 + 1], bb2 = sbl[tx * 5 + 2];
    const float bb3 = sbl[tx * 5 + 3], bb4 = sbl[tx * 5 + 4];

#pragma unroll
    for (int i = 0; i < 4; i++) {
#pragma unroll
        for (int half = 0; half < 2; half++) {
            int r0 = rowBase + ty * 8 + 2 * i + half;
            float2 q0 = *(float2*)&acc[i][0];
            float2 q1 = *(float2*)&acc[i][1];
            float2 q2 = *(float2*)&acc[i][2];
            float2 q3 = *(float2*)&acc[i][3];
            float2 q4 = *(float2*)&acc[i][4];
            float l0 = (half ? q0.y : q0.x) + bb0;
            float l1 = (half ? q1.y : q1.x) + bb1;
            float l2 = (half ? q2.y : q2.x) + bb2;
            float l3 = (half ? q3.y : q3.x) + bb3;
            float l4 = (half ? q4.y : q4.x) + bb4;

            float m = fmaxf(fmaxf(fmaxf(l0, l1), fmaxf(l2, l3)), l4);
            m = fmaxf(m, __shfl_xor_sync(0xffffffffu, m, 1));
            m = fmaxf(m, __shfl_xor_sync(0xffffffffu, m, 2));
            m = fmaxf(m, __shfl_xor_sync(0xffffffffu, m, 4));
            float se = __expf(l0 - m) + __expf(l1 - m) + __expf(l2 - m)
                     + __expf(l3 - m) + __expf(l4 - m);
            se += __shfl_xor_sync(0xffffffffu, se, 1);
            se += __shfl_xor_sync(0xffffffffu, se, 2);
            se += __shfl_xor_sync(0xffffffffu, se, 4);
            float lse = __logf(se) + m;

            if (r0 < n) {
                float* op = out + (size_t)r0 * C + tx * 5;
                op[0] = l0 - lse; op[1] = l1 - lse; op[2] = l2 - lse;
                op[3] = l3 - lse; op[4] = l4 - lse;
            }
        }
    }
}

// ---------------------------------------------------------------------------
// launch
// ---------------------------------------------------------------------------
extern "C" void kernel_launch(void* const* d_in, const int* in_sizes, int n_in,
                              void* d_out, int out_size) {
    const float* x   = (const float*)d_in[0];
    const int*   ei  = (const int*)d_in[1];
    const float* w0  = (const float*)d_in[2];
    const float* b0  = (const float*)d_in[3];
    const float* w1  = (const float*)d_in[4];
    const float* b1  = (const float*)d_in[5];
    const float* wl  = (const float*)d_in[6];
    const float* bl  = (const float*)d_in[7];
    float* out = (float*)d_out;

    const int n = in_sizes[0] / H;
    const int e = in_sizes[1] / 2;
    const int* src = ei;
    const int* dst = ei + e;

    float *dinv, *lin, *agg, *h0, *csr_w;
    __nv_bfloat16* linb;
    int *cnt, *rowstart, *cursor, *bsum, *csr_src;
    cudaGetSymbolAddress((void**)&dinv,     g_dinv);
    cudaGetSymbolAddress((void**)&cnt,      g_cnt);
    cudaGetSymbolAddress((void**)&rowstart, g_rowstart);
    cudaGetSymbolAddress((void**)&cursor,   g_cursor);
    cudaGetSymbolAddress((void**)&bsum,     g_bsum);
    cudaGetSymbolAddress((void**)&csr_src,  g_csr_src);
    cudaGetSymbolAddress((void**)&csr_w,    g_csr_w);
    cudaGetSymbolAddress((void**)&lin,      g_lin);
    cudaGetSymbolAddress((void**)&linb,     g_linb);
    cudaGetSymbolAddress((void**)&agg,      g_agg);
    cudaGetSymbolAddress((void**)&h0,       g_h0);

    static cudaStream_t s2 = nullptr;
    static cudaEvent_t evFork = nullptr, evJoin = nullptr;
    if (!s2) {
        cudaStreamCreateWithFlags(&s2, cudaStreamNonBlocking);
        cudaEventCreateWithFlags(&evFork, cudaEventDisableTiming);
        cudaEventCreateWithFlags(&evJoin, cudaEventDisableTiming);
    }

    const int TB = 256;
    const int nb = (n + SEG - 1) / SEG;
    const int gemmBlocks   = (n + 63) / 64;
    const int gatherBlocks = (n * 32 + TB - 1) / TB;

    // fork: CSR build on s2, GEMM0 on main stream
    cudaEventRecord(evFork, 0);
    cudaStreamWaitEvent(s2, evFork, 0);

    cudaMemsetAsync(cnt, 0, n * sizeof(int), s2);
    k_count  <<<(e + TB - 1) / TB, TB, 0, s2>>>(dst, cnt, e);
    k_dinv   <<<(n + TB - 1) / TB, TB, 0, s2>>>(cnt, dinv, n);
    k_scan1  <<<nb, SEG, 0, s2>>>(cnt, rowstart, bsum, n);
    k_scan2  <<<1, 256, 0, s2>>>(bsum, rowstart, nb, n);
    k_scan3  <<<(n + TB - 1) / TB, TB, 0, s2>>>(rowstart, bsum, cursor, n);
    k_scatter<<<(e + TB - 1) / TB, TB, 0, s2>>>(src, dst, dinv, cursor,
                                                csr_src, csr_w, e);
    cudaEventRecord(evJoin, s2);

    k_gemm128<<<gemmBlocks, TB>>>(x, w0, lin, linb, n);

    cudaStreamWaitEvent(0, evJoin, 0);

    k_gather <<<gatherBlocks, TB>>>(lin, linb, dinv, rowstart, csr_src, csr_w,
                                    b0, nullptr, h0, n);
    k_gemm128<<<gemmBlocks, TB>>>(h0, w1, lin, linb, n);
    k_gather <<<gatherBlocks, TB>>>(lin, linb, dinv, rowstart, csr_src, csr_w,
                                    b1, h0, agg, n);
    k_cls_gemm<<<(n + 255) / 256, TB>>>(agg, wl, bl, out, n);
}